// round 16
// baseline (speedup 1.0000x reference)
#include <cuda_runtime.h>
#include <math.h>

#define BATCH 2
#define NN    256
#define CC    64
#define OO    64
#define GK    8
#define CIN2  128   // C + O for update layer
#define SPB   4     // samples per block

// ---------------- device scratch (no allocs allowed) ----------------
__device__ float  g_alpha[BATCH * NN * NN];  // softmax attention
__device__ float  g_msg[BATCH * NN * OO];    // message values [sample][o]
// update weights packed as float4 groups: group gi covers ck = q*144 + i*4 .. +3
// (gi = q*36 + i, q in 0..7); float layout: g_uw4[gi*256 + o*4 + comp]
__device__ float  g_uw4[CIN2 * 9 * OO];

// Uniform cubic B-spline: writes 8 basis values at p[g*SPB], g=0..7; returns SiLU.
__device__ __forceinline__ void basis8_s(float v, float* p, float& sil) {
#pragma unroll
    for (int g = 0; g < GK; g++) p[g * SPB] = 0.f;
    sil = v * __frcp_rn(1.f + __expf(-v));
    float s  = (v + 2.2f) * 2.5f;       // (v - g0)/h,  g0=-2.2, h=0.4
    float fj = floorf(s);
    int   ji = (int)fj;
    if (ji >= 0 && ji <= 10) {
        float u  = s - fj;
        float u2 = u * u, u3 = u2 * u;
        float um = 1.f - u;
        float b0 = um * um * um * (1.f / 6.f);
        float b1 = (3.f * u3 - 6.f * u2 + 4.f) * (1.f / 6.f);
        float b2 = (-3.f * u3 + 3.f * u2 + 3.f * u + 1.f) * (1.f / 6.f);
        float b3 = u3 * (1.f / 6.f);
        int m = ji - 3;
        if (m     >= 0 && m     < GK) p[ m      * SPB] = b0;
        if (m + 1 >= 0 && m + 1 < GK) p[(m + 1) * SPB] = b1;
        if (m + 2 >= 0 && m + 2 < GK) p[(m + 2) * SPB] = b2;
        if (m + 3 >= 0 && m + 3 < GK) p[(m + 3) * SPB] = b3;
    }
}

// ---------------- K1: fused {uw-pack | msg | energy+softmax} ----------------
struct EnergyS {
    float4 spoly[CC * 11];     // 11264 B
    float  sfb[CC];
    float  sxi[CC];
    float  wred[8];
};
struct MsgS {
    float4 sval[CC * 9];       // [ck] -> 4 samples
    float  part[4][SPB][OO];
};
union FusedS { EnergyS e; MsgS m; };

#define NB_UWP 72
#define NB_MSG 128

__global__ __launch_bounds__(256, 3) void fused_kernel(const float* __restrict__ x,
                                                       const int*   __restrict__ adj,
                                                       const float* __restrict__ fw_base,
                                                       const float* __restrict__ fw_spline,
                                                       const float* __restrict__ fw_scaler,
                                                       const float* __restrict__ mw_base,
                                                       const float* __restrict__ mw_spline,
                                                       const float* __restrict__ mw_scaler,
                                                       const float* __restrict__ uw_base,
                                                       const float* __restrict__ uw_spline,
                                                       const float* __restrict__ uw_scaler) {
    __shared__ FusedS u;
    int t = threadIdx.x;

    if (blockIdx.x < NB_UWP) {
        // ---- update-weight pack: coalesced read, scattered write ----
        int tid = blockIdx.x * 256 + t;          // 18432 threads
        // spline part: 65536 linear elements of uw_spline [o][c][k2]
        for (int lin = tid; lin < OO * CIN2 * 8; lin += NB_UWP * 256) {
            int o  = lin >> 10;
            int c  = (lin >> 3) & 127;
            int k2 = lin & 7;
            float w = uw_spline[lin] * __ldg(uw_scaler + (lin >> 3));
            int ck = c * 9 + k2 + 1;
            int q  = ck / 144;
            int r  = ck - q * 144;
            g_uw4[((q * 36 + (r >> 2)) << 8) + (o << 2) + (r & 3)] = w;
        }
        // base part: 8192 linear elements of uw_base [o][c]
        for (int lin = tid; lin < OO * CIN2; lin += NB_UWP * 256) {
            int o = lin >> 7;
            int c = lin & 127;
            float w = uw_base[lin];
            int ck = c * 9;
            int q  = ck / 144;
            int r  = ck - q * 144;
            g_uw4[((q * 36 + (r >> 2)) << 8) + (o << 2) + (r & 3)] = w;
        }
        return;
    }

    if (blockIdx.x < NB_UWP + NB_MSG) {
        // ---- msg: 4 samples, 256 threads, weights read in ORIGINAL layout ----
        int s0 = (blockIdx.x - NB_UWP) * SPB;
        float* svf = (float*)u.m.sval;
        {
            int s = t >> 6, c = t & 63;
            float v = x[(s0 + s) * CC + c];
            float sil;
            basis8_s(v, svf + (c * 9 + 1) * SPB + s, sil);
            svf[(c * 9) * SPB + s] = sil;
        }
        __syncthreads();

        int o = t & 63, q = t >> 6;          // q in 0..3, 16 channels each
        const float4* wsp = (const float4*)(mw_spline + (o * CC + q * 16) * GK); // 2 float4 per c
        const float*  wba = mw_base   + o * CC + q * 16;
        const float*  wsc = mw_scaler + o * CC + q * 16;
        float4 acc = make_float4(0.f, 0.f, 0.f, 0.f);
#pragma unroll
        for (int ci = 0; ci < 16; ci++) {
            int c = q * 16 + ci;
            float4 wA = wsp[ci * 2];
            float4 wB = wsp[ci * 2 + 1];
            float  sc = wsc[ci];
            float  wb = wba[ci];
            const float4* vp = u.m.sval + c * 9;
            float4 v0 = vp[0], v1 = vp[1], v2 = vp[2], v3 = vp[3], v4 = vp[4];
            float4 v5 = vp[5], v6 = vp[6], v7 = vp[7], v8 = vp[8];
            float w1 = wA.x * sc, w2 = wA.y * sc, w3 = wA.z * sc, w4 = wA.w * sc;
            float w5 = wB.x * sc, w6 = wB.y * sc, w7 = wB.z * sc, w8 = wB.w * sc;
            acc.x = fmaf(v0.x, wb, acc.x); acc.y = fmaf(v0.y, wb, acc.y);
            acc.z = fmaf(v0.z, wb, acc.z); acc.w = fmaf(v0.w, wb, acc.w);
            acc.x = fmaf(v1.x, w1, acc.x); acc.y = fmaf(v1.y, w1, acc.y);
            acc.z = fmaf(v1.z, w1, acc.z); acc.w = fmaf(v1.w, w1, acc.w);
            acc.x = fmaf(v2.x, w2, acc.x); acc.y = fmaf(v2.y, w2, acc.y);
            acc.z = fmaf(v2.z, w2, acc.z); acc.w = fmaf(v2.w, w2, acc.w);
            acc.x = fmaf(v3.x, w3, acc.x); acc.y = fmaf(v3.y, w3, acc.y);
            acc.z = fmaf(v3.z, w3, acc.z); acc.w = fmaf(v3.w, w3, acc.w);
            acc.x = fmaf(v4.x, w4, acc.x); acc.y = fmaf(v4.y, w4, acc.y);
            acc.z = fmaf(v4.z, w4, acc.z); acc.w = fmaf(v4.w, w4, acc.w);
            acc.x = fmaf(v5.x, w5, acc.x); acc.y = fmaf(v5.y, w5, acc.y);
            acc.z = fmaf(v5.z, w5, acc.z); acc.w = fmaf(v5.w, w5, acc.w);
            acc.x = fmaf(v6.x, w6, acc.x); acc.y = fmaf(v6.y, w6, acc.y);
            acc.z = fmaf(v6.z, w6, acc.z); acc.w = fmaf(v6.w, w6, acc.w);
            acc.x = fmaf(v7.x, w7, acc.x); acc.y = fmaf(v7.y, w7, acc.y);
            acc.z = fmaf(v7.z, w7, acc.z); acc.w = fmaf(v7.w, w7, acc.w);
            acc.x = fmaf(v8.x, w8, acc.x); acc.y = fmaf(v8.y, w8, acc.y);
            acc.z = fmaf(v8.z, w8, acc.z); acc.w = fmaf(v8.w, w8, acc.w);
        }
        u.m.part[q][0][o] = acc.x; u.m.part[q][1][o] = acc.y;
        u.m.part[q][2][o] = acc.z; u.m.part[q][3][o] = acc.w;
        __syncthreads();
        {
            int s = t >> 6, c = t & 63;
            float r = u.m.part[0][s][c] + u.m.part[1][s][c] +
                      u.m.part[2][s][c] + u.m.part[3][s][c];
            g_msg[(s0 + s) * OO + c] = r;
        }
        return;
    }

    // ---------------- energy + mask + softmax ----------------
    int bid = blockIdx.x - (NB_UWP + NB_MSG);
    int b = bid >> 8;
    int i = bid & 255;

    // build piecewise-cubic table for the energy spline, in-block
    for (int idx = t; idx < CC * 11; idx += 256) {
        int c = idx / 11, j = idx - c * 11;
        const float P[4][4] = { {1.f, -3.f, 3.f, -1.f},
                                {4.f,  0.f, -6.f, 3.f},
                                {1.f,  3.f, 3.f, -3.f},
                                {0.f,  0.f, 0.f,  1.f} };
        float a0 = 0.f, a1 = 0.f, a2 = 0.f, a3 = 0.f;
#pragma unroll
        for (int tt = 0; tt < 4; tt++) {
            int m = j - 3 + tt;
            if (m >= 0 && m < GK) {
                float w = __ldg(fw_spline + c * GK + m) * __ldg(fw_scaler + c) * (1.f / 6.f);
                a0 += w * P[tt][0]; a1 += w * P[tt][1];
                a2 += w * P[tt][2]; a3 += w * P[tt][3];
            }
        }
        u.e.spoly[idx] = make_float4(a0, a1, a2, a3);
    }
    if (t < CC) {
        u.e.sfb[t] = fw_base[t];
        u.e.sxi[t] = x[(b * NN + i) * CC + t];
    }
    __syncthreads();

    // thread t's own row x[b][t][:] — contiguous, loaded as float4 chunks
    const float4* xr = (const float4*)(x + (b * NN + t) * CC);
    int adj_v = adj[(b * NN + i) * NN + t];

    float e = 0.f;
#pragma unroll 4
    for (int ch = 0; ch < 16; ch++) {
        float4 v4 = xr[ch];
        float rv[4] = { u.e.sxi[ch * 4 + 0] - v4.x,
                        u.e.sxi[ch * 4 + 1] - v4.y,
                        u.e.sxi[ch * 4 + 2] - v4.z,
                        u.e.sxi[ch * 4 + 3] - v4.w };
#pragma unroll
        for (int k = 0; k < 4; k++) {
            int   c = ch * 4 + k;
            float r = rv[k];
            e = fmaf(u.e.sfb[c] * r, __frcp_rn(1.f + __expf(-r)), e);
            float s  = (r + 2.2f) * 2.5f;
            float fj = floorf(s);
            int   ji = (int)fj;
            if (ji >= 0 && ji <= 10) {
                float uu = s - fj;
                float4 a = u.e.spoly[c * 11 + ji];
                e += fmaf(fmaf(fmaf(a.w, uu, a.z), uu, a.y), uu, a.x);
            }
        }
    }
    if (adj_v == 0) e = -1e9f;

    int lane = t & 31, w = t >> 5;
    float m = e;
#pragma unroll
    for (int ofs = 16; ofs; ofs >>= 1)
        m = fmaxf(m, __shfl_xor_sync(0xffffffffu, m, ofs));
    if (lane == 0) u.e.wred[w] = m;
    __syncthreads();
    float mm = u.e.wred[0];
#pragma unroll
    for (int k = 1; k < 8; k++) mm = fmaxf(mm, u.e.wred[k]);

    float ev = __expf(e - mm);
    float sum = ev;
#pragma unroll
    for (int ofs = 16; ofs; ofs >>= 1)
        sum += __shfl_xor_sync(0xffffffffu, sum, ofs);
    __syncthreads();
    if (lane == 0) u.e.wred[w] = sum;
    __syncthreads();
    float tot = u.e.wred[0];
#pragma unroll
    for (int k = 1; k < 8; k++) tot += u.e.wred[k];

    g_alpha[(b * NN + i) * NN + t] = ev * __frcp_rn(tot);
}

// ---------------- K2: aggr = alpha @ msg ; out = kan_linear([x, aggr], uw_*) ----------------
__global__ __launch_bounds__(512) void update_kernel(const float* __restrict__ x,
                                                     float* __restrict__ out) {
    int s0 = blockIdx.x * SPB;      // 4 samples, same batch within block
    int b  = s0 >> 8;
    int t  = threadIdx.x;

    __shared__ float4 salT[NN];          // [j] -> 4 samples, 4096 B
    __shared__ float4 sval[CIN2 * 9];    // [ck] -> 4 samples, 18432 B
    __shared__ float  part[8][SPB][OO];  // 8192 B
    __shared__ float  aggr_s[SPB][OO];   // 1024 B

    {
        float* sa = (float*)salT;
        for (int idx = t; idx < NN * SPB; idx += 512) {
            int j = idx >> 2, s = idx & 3;
            sa[idx] = g_alpha[(s0 + s) * NN + j];
        }
    }
    __syncthreads();

    int o = t & 63, q = t >> 6;          // q in 0..7
    // aggr: eighth q sums j = q*32 .. q*32+31 for all 4 samples
    {
        const float* mb = g_msg + b * NN * OO + o;
        float4 acc = make_float4(0.f, 0.f, 0.f, 0.f);
#pragma unroll
        for (int j = q * 32; j < q * 32 + 32; j++) {
            float  w  = mb[j * OO];
            float4 a4 = salT[j];
            acc.x = fmaf(a4.x, w, acc.x);
            acc.y = fmaf(a4.y, w, acc.y);
            acc.z = fmaf(a4.z, w, acc.z);
            acc.w = fmaf(a4.w, w, acc.w);
        }
        part[q][0][o] = acc.x; part[q][1][o] = acc.y;
        part[q][2][o] = acc.z; part[q][3][o] = acc.w;
    }
    __syncthreads();
    if (t < 256) {
        int s = t >> 6, c = t & 63;
        float a = 0.f;
#pragma unroll
        for (int k = 0; k < 8; k++) a += part[k][s][c];
        aggr_s[s][c] = a;
    }
    __syncthreads();

    // basis for 128 channels: 512 threads = 4 samples x 128 channels
    {
        int s2 = t >> 7, c2 = t & 127;
        float v = (c2 < CC) ? x[(s0 + s2) * CC + c2] : aggr_s[s2][c2 - CC];
        float* svf = (float*)sval;
        float sil;
        basis8_s(v, svf + (c2 * 9 + 1) * SPB + s2, sil);
        svf[(c2 * 9) * SPB + s2] = sil;
    }
    __syncthreads();

    // main reduction: eighth q handles channels q*16..q*16+15 (144 k-values, 36 float4 groups)
    {
        const float4* wp = (const float4*)g_uw4 + q * 36 * 64 + o;
        const float4* vp = sval + q * 144;
        float4 acc = make_float4(0.f, 0.f, 0.f, 0.f);
#pragma unroll
        for (int i = 0; i < 36; i++) {
            float4 w  = wp[i * 64];
            float4 v0 = vp[i * 4 + 0];
            float4 v1 = vp[i * 4 + 1];
            float4 v2 = vp[i * 4 + 2];
            float4 v3 = vp[i * 4 + 3];
            acc.x = fmaf(v0.x, w.x, fmaf(v1.x, w.y, fmaf(v2.x, w.z, fmaf(v3.x, w.w, acc.x))));
            acc.y = fmaf(v0.y, w.x, fmaf(v1.y, w.y, fmaf(v2.y, w.z, fmaf(v3.y, w.w, acc.y))));
            acc.z = fmaf(v0.z, w.x, fmaf(v1.z, w.y, fmaf(v2.z, w.z, fmaf(v3.z, w.w, acc.z))));
            acc.w = fmaf(v0.w, w.x, fmaf(v1.w, w.y, fmaf(v2.w, w.z, fmaf(v3.w, w.w, acc.w))));
        }
        part[q][0][o] = acc.x; part[q][1][o] = acc.y;
        part[q][2][o] = acc.z; part[q][3][o] = acc.w;
    }
    __syncthreads();
    if (t < 256) {
        int s = t >> 6, c = t & 63;
        float r = 0.f;
#pragma unroll
        for (int k = 0; k < 8; k++) r += part[k][s][c];
        out[(s0 + s) * OO + c] = r;
    }
}

// ---------------- launch ----------------
extern "C" void kernel_launch(void* const* d_in, const int* in_sizes, int n_in,
                              void* d_out, int out_size) {
    const float* x         = (const float*)d_in[0];
    const int*   adj       = (const int*)  d_in[1];
    const float* fw_base   = (const float*)d_in[2];
    const float* fw_spline = (const float*)d_in[3];
    const float* fw_scaler = (const float*)d_in[4];
    const float* mw_base   = (const float*)d_in[5];
    const float* mw_spline = (const float*)d_in[6];
    const float* mw_scaler = (const float*)d_in[7];
    const float* uw_base   = (const float*)d_in[8];
    const float* uw_spline = (const float*)d_in[9];
    const float* uw_scaler = (const float*)d_in[10];
    float* out = (float*)d_out;

    fused_kernel<<<NB_UWP + NB_MSG + BATCH * NN, 256>>>(x, adj, fw_base, fw_spline, fw_scaler,
                                                        mw_base, mw_spline, mw_scaler,
                                                        uw_base, uw_spline, uw_scaler);
    update_kernel<<<(BATCH * NN) / SPB, 512>>>(x, out);
}

// round 17
// speedup vs baseline: 1.0172x; 1.0172x over previous
#include <cuda_runtime.h>
#include <math.h>

#define BATCH 2
#define NN    256
#define CC    64
#define OO    64
#define GK    8
#define CIN2  128   // C + O for update layer
#define SPB   4     // samples per block

// ---------------- device scratch (no allocs allowed) ----------------
__device__ float  g_alpha[BATCH * NN * NN];  // softmax attention
__device__ float  g_msg[BATCH * NN * OO];    // message values [sample][o]
// update weights packed as float4 groups: group gi covers ck = q*144 + i*4 .. +3
// (gi = q*36 + i, q in 0..7); float layout: g_uw4[gi*256 + o*4 + comp]
__device__ float  g_uw4[CIN2 * 9 * OO];

// Uniform cubic B-spline: writes 8 basis values at p[g*SPB], g=0..7; returns SiLU.
__device__ __forceinline__ void basis8_s(float v, float* p, float& sil) {
#pragma unroll
    for (int g = 0; g < GK; g++) p[g * SPB] = 0.f;
    sil = v * __frcp_rn(1.f + __expf(-v));
    float s  = (v + 2.2f) * 2.5f;       // (v - g0)/h,  g0=-2.2, h=0.4
    float fj = floorf(s);
    int   ji = (int)fj;
    if (ji >= 0 && ji <= 10) {
        float u  = s - fj;
        float u2 = u * u, u3 = u2 * u;
        float um = 1.f - u;
        float b0 = um * um * um * (1.f / 6.f);
        float b1 = (3.f * u3 - 6.f * u2 + 4.f) * (1.f / 6.f);
        float b2 = (-3.f * u3 + 3.f * u2 + 3.f * u + 1.f) * (1.f / 6.f);
        float b3 = u3 * (1.f / 6.f);
        int m = ji - 3;
        if (m     >= 0 && m     < GK) p[ m      * SPB] = b0;
        if (m + 1 >= 0 && m + 1 < GK) p[(m + 1) * SPB] = b1;
        if (m + 2 >= 0 && m + 2 < GK) p[(m + 2) * SPB] = b2;
        if (m + 3 >= 0 && m + 3 < GK) p[(m + 3) * SPB] = b3;
    }
}

// ---------------- K1: fused {uw-pack | msg | energy+softmax} ----------------
struct EnergyS {
    float4 spoly[CC * 11];     // 11264 B
    float  sfb[CC];
    float  sxi[CC];
    float  wred[8];
};
struct MsgS {
    float4 sval[CC * 9];       // [ck] -> 4 samples
    float  part[4][SPB][OO];
};
union FusedS { EnergyS e; MsgS m; };

#define NB_UWP 72
#define NB_MSG 128

__global__ __launch_bounds__(256, 3) void fused_kernel(const float* __restrict__ x,
                                                       const int*   __restrict__ adj,
                                                       const float* __restrict__ fw_base,
                                                       const float* __restrict__ fw_spline,
                                                       const float* __restrict__ fw_scaler,
                                                       const float* __restrict__ mw_base,
                                                       const float* __restrict__ mw_spline,
                                                       const float* __restrict__ mw_scaler,
                                                       const float* __restrict__ uw_base,
                                                       const float* __restrict__ uw_spline,
                                                       const float* __restrict__ uw_scaler) {
    __shared__ FusedS u;
    int t = threadIdx.x;

    if (blockIdx.x < NB_UWP) {
        // ---- update-weight pack: coalesced read, scattered write ----
        int tid = blockIdx.x * 256 + t;          // 18432 threads
        // spline part: 65536 linear elements of uw_spline [o][c][k2]
        for (int lin = tid; lin < OO * CIN2 * 8; lin += NB_UWP * 256) {
            int o  = lin >> 10;
            int c  = (lin >> 3) & 127;
            int k2 = lin & 7;
            float w = uw_spline[lin] * __ldg(uw_scaler + (lin >> 3));
            int ck = c * 9 + k2 + 1;
            int q  = ck / 144;
            int r  = ck - q * 144;
            g_uw4[((q * 36 + (r >> 2)) << 8) + (o << 2) + (r & 3)] = w;
        }
        // base part: 8192 linear elements of uw_base [o][c]
        for (int lin = tid; lin < OO * CIN2; lin += NB_UWP * 256) {
            int o = lin >> 7;
            int c = lin & 127;
            float w = uw_base[lin];
            int ck = c * 9;
            int q  = ck / 144;
            int r  = ck - q * 144;
            g_uw4[((q * 36 + (r >> 2)) << 8) + (o << 2) + (r & 3)] = w;
        }
        return;
    }

    if (blockIdx.x < NB_UWP + NB_MSG) {
        // ---- msg: 4 samples, 256 threads, weights read in ORIGINAL layout ----
        int s0 = (blockIdx.x - NB_UWP) * SPB;
        float* svf = (float*)u.m.sval;
        {
            int s = t >> 6, c = t & 63;
            float v = x[(s0 + s) * CC + c];
            float sil;
            basis8_s(v, svf + (c * 9 + 1) * SPB + s, sil);
            svf[(c * 9) * SPB + s] = sil;
        }
        __syncthreads();

        int o = t & 63, q = t >> 6;          // q in 0..3, 16 channels each
        const float4* wsp = (const float4*)(mw_spline + (o * CC + q * 16) * GK); // 2 float4 per c
        const float*  wba = mw_base   + o * CC + q * 16;
        const float*  wsc = mw_scaler + o * CC + q * 16;
        float4 acc = make_float4(0.f, 0.f, 0.f, 0.f);
#pragma unroll
        for (int ci = 0; ci < 16; ci++) {
            int c = q * 16 + ci;
            float4 wA = wsp[ci * 2];
            float4 wB = wsp[ci * 2 + 1];
            float  sc = wsc[ci];
            float  wb = wba[ci];
            const float4* vp = u.m.sval + c * 9;
            float4 v0 = vp[0], v1 = vp[1], v2 = vp[2], v3 = vp[3], v4 = vp[4];
            float4 v5 = vp[5], v6 = vp[6], v7 = vp[7], v8 = vp[8];
            float w1 = wA.x * sc, w2 = wA.y * sc, w3 = wA.z * sc, w4 = wA.w * sc;
            float w5 = wB.x * sc, w6 = wB.y * sc, w7 = wB.z * sc, w8 = wB.w * sc;
            acc.x = fmaf(v0.x, wb, acc.x); acc.y = fmaf(v0.y, wb, acc.y);
            acc.z = fmaf(v0.z, wb, acc.z); acc.w = fmaf(v0.w, wb, acc.w);
            acc.x = fmaf(v1.x, w1, acc.x); acc.y = fmaf(v1.y, w1, acc.y);
            acc.z = fmaf(v1.z, w1, acc.z); acc.w = fmaf(v1.w, w1, acc.w);
            acc.x = fmaf(v2.x, w2, acc.x); acc.y = fmaf(v2.y, w2, acc.y);
            acc.z = fmaf(v2.z, w2, acc.z); acc.w = fmaf(v2.w, w2, acc.w);
            acc.x = fmaf(v3.x, w3, acc.x); acc.y = fmaf(v3.y, w3, acc.y);
            acc.z = fmaf(v3.z, w3, acc.z); acc.w = fmaf(v3.w, w3, acc.w);
            acc.x = fmaf(v4.x, w4, acc.x); acc.y = fmaf(v4.y, w4, acc.y);
            acc.z = fmaf(v4.z, w4, acc.z); acc.w = fmaf(v4.w, w4, acc.w);
            acc.x = fmaf(v5.x, w5, acc.x); acc.y = fmaf(v5.y, w5, acc.y);
            acc.z = fmaf(v5.z, w5, acc.z); acc.w = fmaf(v5.w, w5, acc.w);
            acc.x = fmaf(v6.x, w6, acc.x); acc.y = fmaf(v6.y, w6, acc.y);
            acc.z = fmaf(v6.z, w6, acc.z); acc.w = fmaf(v6.w, w6, acc.w);
            acc.x = fmaf(v7.x, w7, acc.x); acc.y = fmaf(v7.y, w7, acc.y);
            acc.z = fmaf(v7.z, w7, acc.z); acc.w = fmaf(v7.w, w7, acc.w);
            acc.x = fmaf(v8.x, w8, acc.x); acc.y = fmaf(v8.y, w8, acc.y);
            acc.z = fmaf(v8.z, w8, acc.z); acc.w = fmaf(v8.w, w8, acc.w);
        }
        u.m.part[q][0][o] = acc.x; u.m.part[q][1][o] = acc.y;
        u.m.part[q][2][o] = acc.z; u.m.part[q][3][o] = acc.w;
        __syncthreads();
        {
            int s = t >> 6, c = t & 63;
            float r = u.m.part[0][s][c] + u.m.part[1][s][c] +
                      u.m.part[2][s][c] + u.m.part[3][s][c];
            g_msg[(s0 + s) * OO + c] = r;
        }
        return;
    }

    // ---------------- energy + mask + softmax ----------------
    int bid = blockIdx.x - (NB_UWP + NB_MSG);
    int b = bid >> 8;
    int i = bid & 255;

    // build piecewise-cubic table for the energy spline, in-block
    for (int idx = t; idx < CC * 11; idx += 256) {
        int c = idx / 11, j = idx - c * 11;
        const float P[4][4] = { {1.f, -3.f, 3.f, -1.f},
                                {4.f,  0.f, -6.f, 3.f},
                                {1.f,  3.f, 3.f, -3.f},
                                {0.f,  0.f, 0.f,  1.f} };
        float a0 = 0.f, a1 = 0.f, a2 = 0.f, a3 = 0.f;
#pragma unroll
        for (int tt = 0; tt < 4; tt++) {
            int m = j - 3 + tt;
            if (m >= 0 && m < GK) {
                float w = __ldg(fw_spline + c * GK + m) * __ldg(fw_scaler + c) * (1.f / 6.f);
                a0 += w * P[tt][0]; a1 += w * P[tt][1];
                a2 += w * P[tt][2]; a3 += w * P[tt][3];
            }
        }
        u.e.spoly[idx] = make_float4(a0, a1, a2, a3);
    }
    if (t < CC) {
        u.e.sfb[t] = fw_base[t];
        u.e.sxi[t] = x[(b * NN + i) * CC + t];
    }
    __syncthreads();

    // thread t's own row x[b][t][:] — contiguous, loaded as float4 chunks
    const float4* xr = (const float4*)(x + (b * NN + t) * CC);
    int adj_v = adj[(b * NN + i) * NN + t];

    float e = 0.f;
#pragma unroll 4
    for (int ch = 0; ch < 16; ch++) {
        float4 v4 = xr[ch];
        float rv[4] = { u.e.sxi[ch * 4 + 0] - v4.x,
                        u.e.sxi[ch * 4 + 1] - v4.y,
                        u.e.sxi[ch * 4 + 2] - v4.z,
                        u.e.sxi[ch * 4 + 3] - v4.w };
#pragma unroll
        for (int k = 0; k < 4; k++) {
            int   c = ch * 4 + k;
            float r = rv[k];
            e = fmaf(u.e.sfb[c] * r, __frcp_rn(1.f + __expf(-r)), e);
            float s  = (r + 2.2f) * 2.5f;
            float fj = floorf(s);
            int   ji = (int)fj;
            if (ji >= 0 && ji <= 10) {
                float uu = s - fj;
                float4 a = u.e.spoly[c * 11 + ji];
                e += fmaf(fmaf(fmaf(a.w, uu, a.z), uu, a.y), uu, a.x);
            }
        }
    }
    if (adj_v == 0) e = -1e9f;

    int lane = t & 31, w = t >> 5;
    float m = e;
#pragma unroll
    for (int ofs = 16; ofs; ofs >>= 1)
        m = fmaxf(m, __shfl_xor_sync(0xffffffffu, m, ofs));
    if (lane == 0) u.e.wred[w] = m;
    __syncthreads();
    float mm = u.e.wred[0];
#pragma unroll
    for (int k = 1; k < 8; k++) mm = fmaxf(mm, u.e.wred[k]);

    float ev = __expf(e - mm);
    float sum = ev;
#pragma unroll
    for (int ofs = 16; ofs; ofs >>= 1)
        sum += __shfl_xor_sync(0xffffffffu, sum, ofs);
    __syncthreads();
    if (lane == 0) u.e.wred[w] = sum;
    __syncthreads();
    float tot = u.e.wred[0];
#pragma unroll
    for (int k = 1; k < 8; k++) tot += u.e.wred[k];

    g_alpha[(b * NN + i) * NN + t] = ev * __frcp_rn(tot);
}

// ---------------- K2: aggr = alpha @ msg ; out = kan_linear([x, aggr], uw_*) ----------------
__global__ __launch_bounds__(512) void update_kernel(const float* __restrict__ x,
                                                     float* __restrict__ out) {
    int s0 = blockIdx.x * SPB;      // 4 samples, same batch within block
    int b  = s0 >> 8;
    int t  = threadIdx.x;

    __shared__ float4 salT[NN];          // [j] -> 4 samples, 4096 B
    __shared__ float4 sval[CIN2 * 9];    // [ck] -> 4 samples, 18432 B
    __shared__ float  part[8][SPB][OO];  // 8192 B
    __shared__ float  aggr_s[SPB][OO];   // 1024 B

    {
        float* sa = (float*)salT;
        for (int idx = t; idx < NN * SPB; idx += 512) {
            int j = idx >> 2, s = idx & 3;
            sa[idx] = g_alpha[(s0 + s) * NN + j];
        }
    }
    __syncthreads();

    int o = t & 63, q = t >> 6;          // q in 0..7
    // aggr: eighth q sums j = q*32 .. q*32+31 for all 4 samples
    {
        const float* mb = g_msg + b * NN * OO + o;
        float4 acc = make_float4(0.f, 0.f, 0.f, 0.f);
#pragma unroll
        for (int j = q * 32; j < q * 32 + 32; j++) {
            float  w  = mb[j * OO];
            float4 a4 = salT[j];
            acc.x = fmaf(a4.x, w, acc.x);
            acc.y = fmaf(a4.y, w, acc.y);
            acc.z = fmaf(a4.z, w, acc.z);
            acc.w = fmaf(a4.w, w, acc.w);
        }
        part[q][0][o] = acc.x; part[q][1][o] = acc.y;
        part[q][2][o] = acc.z; part[q][3][o] = acc.w;
    }
    __syncthreads();
    if (t < 256) {
        int s = t >> 6, c = t & 63;
        float a = 0.f;
#pragma unroll
        for (int k = 0; k < 8; k++) a += part[k][s][c];
        aggr_s[s][c] = a;
    }
    __syncthreads();

    // basis for 128 channels: 512 threads = 4 samples x 128 channels
    {
        int s2 = t >> 7, c2 = t & 127;
        float v = (c2 < CC) ? x[(s0 + s2) * CC + c2] : aggr_s[s2][c2 - CC];
        float* svf = (float*)sval;
        float sil;
        basis8_s(v, svf + (c2 * 9 + 1) * SPB + s2, sil);
        svf[(c2 * 9) * SPB + s2] = sil;
    }
    __syncthreads();

    // main reduction: eighth q handles channels q*16..q*16+15 (144 k-values, 36 float4 groups)
    {
        const float4* wp = (const float4*)g_uw4 + q * 36 * 64 + o;
        const float4* vp = sval + q * 144;
        float4 acc = make_float4(0.f, 0.f, 0.f, 0.f);
#pragma unroll
        for (int i = 0; i < 36; i++) {
            float4 w  = wp[i * 64];
            float4 v0 = vp[i * 4 + 0];
            float4 v1 = vp[i * 4 + 1];
            float4 v2 = vp[i * 4 + 2];
            float4 v3 = vp[i * 4 + 3];
            acc.x = fmaf(v0.x, w.x, fmaf(v1.x, w.y, fmaf(v2.x, w.z, fmaf(v3.x, w.w, acc.x))));
            acc.y = fmaf(v0.y, w.x, fmaf(v1.y, w.y, fmaf(v2.y, w.z, fmaf(v3.y, w.w, acc.y))));
            acc.z = fmaf(v0.z, w.x, fmaf(v1.z, w.y, fmaf(v2.z, w.z, fmaf(v3.z, w.w, acc.z))));
            acc.w = fmaf(v0.w, w.x, fmaf(v1.w, w.y, fmaf(v2.w, w.z, fmaf(v3.w, w.w, acc.w))));
        }
        part[q][0][o] = acc.x; part[q][1][o] = acc.y;
        part[q][2][o] = acc.z; part[q][3][o] = acc.w;
    }
    __syncthreads();
    if (t < 256) {
        int s = t >> 6, c = t & 63;
        float r = 0.f;
#pragma unroll
        for (int k = 0; k < 8; k++) r += part[k][s][c];
        out[(s0 + s) * OO + c] = r;
    }
}

// ---------------- launch ----------------
extern "C" void kernel_launch(void* const* d_in, const int* in_sizes, int n_in,
                              void* d_out, int out_size) {
    const float* x         = (const float*)d_in[0];
    const int*   adj       = (const int*)  d_in[1];
    const float* fw_base   = (const float*)d_in[2];
    const float* fw_spline = (const float*)d_in[3];
    const float* fw_scaler = (const float*)d_in[4];
    const float* mw_base   = (const float*)d_in[5];
    const float* mw_spline = (const float*)d_in[6];
    const float* mw_scaler = (const float*)d_in[7];
    const float* uw_base   = (const float*)d_in[8];
    const float* uw_spline = (const float*)d_in[9];
    const float* uw_scaler = (const float*)d_in[10];
    float* out = (float*)d_out;

    fused_kernel<<<NB_UWP + NB_MSG + BATCH * NN, 256>>>(x, adj, fw_base, fw_spline, fw_scaler,
                                                        mw_base, mw_spline, mw_scaler,
                                                        uw_base, uw_spline, uw_scaler);
    update_kernel<<<(BATCH * NN) / SPB, 512>>>(x, out);
}